// round 1
// baseline (speedup 1.0000x reference)
#include <cuda_runtime.h>
#include <math.h>

// ---------------- device scratch (allocation-free rule: __device__ globals) ----
__device__ __align__(16) float g_W1[288 * 32];
__device__ __align__(16) float g_W2w[3072 * 64];
__device__ __align__(16) float g_W3w[6144 * 128];
__device__ __align__(16) float g_W4w[12288 * 128];
__device__ __align__(16) float g_y1[512 * 32 * 16 * 16];
__device__ __align__(16) float g_y2[512 * 64 * 8 * 8];
__device__ __align__(16) float g_y3[512 * 128 * 4 * 4];
__device__ __align__(16) float g_y4[512 * 128 * 2 * 2];
__device__ __align__(16) float g_part[4 * 2048 * 128];
__device__ float g_A1[64], g_Bb1[64];
__device__ float g_A2[128], g_Bb2[128];
__device__ float g_A3[128], g_Bb3[128];

// ---------------- expansion: [relu(v), B0..B4(v)] --------------------------
// Knots: t_j = (j-2)*2/3 - 1, j=0..7  => t_0 = -7/3, spacing h = 2/3.
// Quadratic uniform B-spline: B_j(x) = Q((x - t_j)/h), Q on [0,3):
//   Q(u) = u^2/2            on [0,1)
//        = -u^2 + 3u - 3/2  on [1,2)
//        = (3-u)^2/2        on [2,3)
__device__ __forceinline__ void expand6(float v, float e[6]) {
    e[0] = fmaxf(v, 0.0f);
    float u = (v + 2.3333333333333335f) * 1.5f;
#pragma unroll
    for (int j = 0; j < 5; j++) {
        float b;
        if (u < 0.0f || u >= 3.0f)      b = 0.0f;
        else if (u < 1.0f)              b = 0.5f * u * u;
        else if (u < 2.0f)              b = fmaf(-u, u, fmaf(3.0f, u, -1.5f));
        else { float t = 3.0f - u;      b = 0.5f * t * t; }
        e[1 + j] = b;
        u -= 1.0f;
    }
}

// ---------------- weight prep: W[(f*6+j)*O + o] ----------------------------
__global__ void prep_weights(const float* __restrict__ bw, const float* __restrict__ sw,
                             const float* __restrict__ sc, float* __restrict__ Wm,
                             int F, int O) {
    int total = F * 6 * O;
    for (int idx = blockIdx.x * blockDim.x + threadIdx.x; idx < total;
         idx += gridDim.x * blockDim.x) {
        int k = idx / O, o = idx - k * O;
        int f = k / 6, j = k - f * 6;
        float v;
        if (j == 0) v = bw[o * F + f];
        else        v = sw[(o * F + f) * 5 + (j - 1)] * sc[o * F + f];
        Wm[idx] = v;
    }
}

// ---------------- fused KAN conv as GEMM -----------------------------------
// One block: BM=64 positions x O outputs. K loop over features, 8 feats (48 K) per step.
// Expansion (+ optional BN of the *input* tensor) fused into the E-tile loader.
template <int O, int C, int Hin, int Hout, int F, bool HASBN, int SPLITK>
__global__ void __launch_bounds__(256) kan_conv(
    const float* __restrict__ in, const float* __restrict__ Wm,
    const float* __restrict__ bnA, const float* __restrict__ bnB,
    float* __restrict__ out) {
    constexpr int BM = 64;
    constexpr int FB = 8;          // features per K step
    constexpr int BK = FB * 6;     // 48
    constexpr int TN = O / 16;     // 2 / 4 / 8
    constexpr int TM = 4;
    constexpr int Win = Hin, Wout = Hout;
    constexpr int HW = Hout * Wout;
    constexpr int Fl = F / SPLITK;

    __shared__ __align__(16) float Es[BK][BM];
    __shared__ __align__(16) float Ws[BK][O];

    const int tid = threadIdx.x;
    const int p0 = blockIdx.x * BM;
    const int fb0 = blockIdx.y * Fl;

    float acc[TM][TN];
#pragma unroll
    for (int i = 0; i < TM; i++)
#pragma unroll
        for (int j = 0; j < TN; j++) acc[i][j] = 0.0f;

    const int ty = tid >> 4, tx = tid & 15;
    const int row0 = ty * TM, col0 = tx * TN;

    for (int fb = fb0; fb < fb0 + Fl; fb += FB) {
        // ---- load W tile (contiguous rows of Wm) ----
        {
            const float* wsrc = Wm + (size_t)fb * 6 * O;
            for (int i = tid * 4; i < BK * O; i += 256 * 4)
                *(float4*)(&Ws[0][0] + i) = *(const float4*)(wsrc + i);
        }
        // ---- load + expand E tile ----
#pragma unroll
        for (int idx = tid; idx < BM * FB; idx += 256) {
            int m = idx & (BM - 1);
            int fl = idx >> 6;                 // BM == 64
            int p = p0 + m;
            int b = p / HW;
            int s = p - b * HW;
            int oh = s / Wout, ow = s - (s / Wout) * Wout;
            int f = fb + fl;
            int c = f >> 4;
            int r = f & 15;
            int kh = r >> 2, kw = r & 3;
            int ih = oh * 2 + kh - 1, iw = ow * 2 + kw - 1;
            float v = 0.0f;
            if (ih >= 0 && ih < Hin && iw >= 0 && iw < Win) {
                v = in[((b * C + c) * Hin + ih) * Win + iw];
                if (HASBN) v = fmaf(v, bnA[c], bnB[c]);
            }
            float e[6];
            expand6(v, e);
#pragma unroll
            for (int j = 0; j < 6; j++) Es[fl * 6 + j][m] = e[j];
        }
        __syncthreads();
        // ---- FMA inner loop ----
#pragma unroll
        for (int k = 0; k < BK; k++) {
            float a[TM], w[TN];
#pragma unroll
            for (int i = 0; i < TM; i++) a[i] = Es[k][row0 + i];
#pragma unroll
            for (int j = 0; j < TN; j++) w[j] = Ws[k][col0 + j];
#pragma unroll
            for (int i = 0; i < TM; i++)
#pragma unroll
                for (int j = 0; j < TN; j++)
                    acc[i][j] = fmaf(a[i], w[j], acc[i][j]);
        }
        __syncthreads();
    }

    if (SPLITK == 1) {
        // NCHW output
#pragma unroll
        for (int i = 0; i < TM; i++) {
            int p = p0 + row0 + i;
            int b = p / HW;
            int s = p - b * HW;
#pragma unroll
            for (int j = 0; j < TN; j++) {
                int o = col0 + j;
                out[(b * O + o) * HW + s] = acc[i][j];
            }
        }
    } else {
        int Ptot = gridDim.x * BM;
#pragma unroll
        for (int i = 0; i < TM; i++) {
            int p = p0 + row0 + i;
#pragma unroll
            for (int j = 0; j < TN; j++) {
                int o = col0 + j;
                out[((size_t)blockIdx.y * Ptot + p) * O + o] = acc[i][j];
            }
        }
    }
}

// ---------------- split-K reduce for layer 4 (P=2048, O=128, 4 splits) -----
__global__ void splitk_reduce4(const float* __restrict__ part, float* __restrict__ out) {
    int idx = blockIdx.x * blockDim.x + threadIdx.x;
    if (idx >= 2048 * 128) return;
    int p = idx >> 7, o = idx & 127;
    float s = 0.0f;
#pragma unroll
    for (int k = 0; k < 4; k++) s += part[((size_t)k * 2048 + p) * 128 + o];
    int b = p >> 2, sp = p & 3;
    out[(b * 128 + o) * 4 + sp] = s;
}

// ---------------- batchnorm stats -> affine (a, b) -------------------------
__global__ void bn_stats(const float* __restrict__ y, int C, int HW,
                         const float* __restrict__ gamma, const float* __restrict__ beta,
                         float* __restrict__ A, float* __restrict__ Bv) {
    int c = blockIdx.x;
    int N = 512 * HW;
    float s = 0.0f, s2 = 0.0f;
    for (int i = threadIdx.x; i < N; i += blockDim.x) {
        int b = i / HW, sp = i - b * HW;
        float v = y[(b * C + c) * HW + sp];
        s += v; s2 = fmaf(v, v, s2);
    }
    __shared__ float sh[2][256];
    sh[0][threadIdx.x] = s; sh[1][threadIdx.x] = s2;
    __syncthreads();
    for (int st = 128; st > 0; st >>= 1) {
        if (threadIdx.x < st) {
            sh[0][threadIdx.x] += sh[0][threadIdx.x + st];
            sh[1][threadIdx.x] += sh[1][threadIdx.x + st];
        }
        __syncthreads();
    }
    if (threadIdx.x == 0) {
        float inv = 1.0f / (float)N;
        float m = sh[0][0] * inv;
        float var = fmaf(-m, m, sh[1][0] * inv);
        float a = gamma[c] * rsqrtf(var + 1e-5f);
        A[c] = a;
        Bv[c] = fmaf(-m, a, beta[c]);
    }
}

// ---------------- head: BN3 + avgpool(2x2) + FC + sigmoid ------------------
__global__ void head_kernel(const float* __restrict__ y4, const float* __restrict__ A,
                            const float* __restrict__ Bv, const float* __restrict__ fcw,
                            const float* __restrict__ fcb, float* __restrict__ out) {
    int b = blockIdx.x;
    int c = threadIdx.x;  // 128
    const float* p = y4 + ((size_t)b * 128 + c) * 4;
    float m = 0.25f * (p[0] + p[1] + p[2] + p[3]);
    float t = fmaf(m, A[c], Bv[c]) * fcw[c];
    __shared__ float sh[128];
    sh[c] = t;
    __syncthreads();
    for (int st = 64; st > 0; st >>= 1) {
        if (c < st) sh[c] += sh[c + st];
        __syncthreads();
    }
    if (c == 0) {
        float z = sh[0] + fcb[0];
        out[b] = 1.0f / (1.0f + expf(-z));
    }
}

// ---------------- launch -----------------------------------------------------
extern "C" void kernel_launch(void* const* d_in, const int* in_sizes, int n_in,
                              void* d_out, int out_size) {
    const float* x   = (const float*)d_in[0];
    const float* bw1 = (const float*)d_in[1];
    const float* sw1 = (const float*)d_in[2];
    const float* sc1 = (const float*)d_in[3];
    const float* bw2 = (const float*)d_in[4];
    const float* sw2 = (const float*)d_in[5];
    const float* sc2 = (const float*)d_in[6];
    const float* bw3 = (const float*)d_in[7];
    const float* sw3 = (const float*)d_in[8];
    const float* sc3 = (const float*)d_in[9];
    const float* bw4 = (const float*)d_in[10];
    const float* sw4 = (const float*)d_in[11];
    const float* sc4 = (const float*)d_in[12];
    const float* g1  = (const float*)d_in[13];
    const float* b1  = (const float*)d_in[14];
    const float* g2  = (const float*)d_in[15];
    const float* b2  = (const float*)d_in[16];
    const float* g3  = (const float*)d_in[17];
    const float* b3  = (const float*)d_in[18];
    const float* fcw = (const float*)d_in[19];
    const float* fcb = (const float*)d_in[20];

    float *W1, *W2, *W3, *W4, *y1, *y2, *y3, *y4, *part;
    float *A1, *Bv1, *A2, *Bv2, *A3, *Bv3;
    cudaGetSymbolAddress((void**)&W1, g_W1);
    cudaGetSymbolAddress((void**)&W2, g_W2w);
    cudaGetSymbolAddress((void**)&W3, g_W3w);
    cudaGetSymbolAddress((void**)&W4, g_W4w);
    cudaGetSymbolAddress((void**)&y1, g_y1);
    cudaGetSymbolAddress((void**)&y2, g_y2);
    cudaGetSymbolAddress((void**)&y3, g_y3);
    cudaGetSymbolAddress((void**)&y4, g_y4);
    cudaGetSymbolAddress((void**)&part, g_part);
    cudaGetSymbolAddress((void**)&A1, g_A1);
    cudaGetSymbolAddress((void**)&Bv1, g_Bb1);
    cudaGetSymbolAddress((void**)&A2, g_A2);
    cudaGetSymbolAddress((void**)&Bv2, g_Bb2);
    cudaGetSymbolAddress((void**)&A3, g_A3);
    cudaGetSymbolAddress((void**)&Bv3, g_Bb3);

    // fold weights: W[(f*6+j), o] = j==0 ? base_w : spline_w*scaler
    prep_weights<<<64, 256>>>(bw1, sw1, sc1, W1, 48, 32);
    prep_weights<<<256, 256>>>(bw2, sw2, sc2, W2, 512, 64);
    prep_weights<<<512, 256>>>(bw3, sw3, sc3, W3, 1024, 128);
    prep_weights<<<1024, 256>>>(bw4, sw4, sc4, W4, 2048, 128);

    // L1: (512,3,32,32) -> (512,32,16,16)
    kan_conv<32, 3, 32, 16, 48, false, 1><<<131072 / 64, 256>>>(x, W1, nullptr, nullptr, y1);
    // L2: -> (512,64,8,8)
    kan_conv<64, 32, 16, 8, 512, false, 1><<<32768 / 64, 256>>>(y1, W2, nullptr, nullptr, y2);
    // BN1 stats on y2
    bn_stats<<<64, 256>>>(y2, 64, 64, g1, b1, A1, Bv1);
    // L3 (BN1 fused into loader): -> (512,128,4,4)
    kan_conv<128, 64, 8, 4, 1024, true, 1><<<8192 / 64, 256>>>(y2, W3, A1, Bv1, y3);
    // BN2 stats on y3
    bn_stats<<<128, 256>>>(y3, 128, 16, g2, b2, A2, Bv2);
    // L4 (BN2 fused, split-K=4): -> partials, then reduce to (512,128,2,2)
    {
        dim3 grid(2048 / 64, 4);
        kan_conv<128, 128, 4, 2, 2048, true, 4><<<grid, 256>>>(y3, W4, A2, Bv2, part);
        splitk_reduce4<<<(2048 * 128 + 255) / 256, 256>>>(part, y4);
    }
    // BN3 stats on y4
    bn_stats<<<128, 256>>>(y4, 128, 4, g3, b3, A3, Bv3);
    // head: BN3 + avgpool + FC + sigmoid -> (512,1)
    head_kernel<<<512, 128>>>(y4, A3, Bv3, fcw, fcb, (float*)d_out);
}

// round 17
// speedup vs baseline: 2.0439x; 2.0439x over previous
#include <cuda_runtime.h>
#include <cuda_bf16.h>
#include <math.h>
#include <stdint.h>

// ===================== device scratch (no allocs allowed) =====================
// bf16 weight images, pre-swizzled per 64-K chunk SMEM layout, hi/lo split.
__device__ __align__(16) unsigned char g_Wh1[384   * 32  * 2];
__device__ __align__(16) unsigned char g_Wl1[384   * 32  * 2];
__device__ __align__(16) unsigned char g_Wh2[4096  * 64  * 2];
__device__ __align__(16) unsigned char g_Wl2[4096  * 64  * 2];
__device__ __align__(16) unsigned char g_Wh3[8192  * 128 * 2];
__device__ __align__(16) unsigned char g_Wl3[8192  * 128 * 2];
__device__ __align__(16) unsigned char g_Wh4[16384 * 128 * 2];
__device__ __align__(16) unsigned char g_Wl4[16384 * 128 * 2];

__device__ __align__(16) float g_y1[512 * 32 * 16 * 16];
__device__ __align__(16) float g_y2[512 * 64 * 8 * 8];
__device__ __align__(16) float g_y3[512 * 128 * 4 * 4];
__device__ __align__(16) float g_y4[512 * 128 * 2 * 2];
__device__ __align__(16) float g_part3[2 * 128 * 8192];
__device__ __align__(16) float g_part4[8 * 128 * 2048];
__device__ float g_A1[64], g_Bb1[64];
__device__ float g_A2[128], g_Bb2[128];
__device__ float g_A3[128], g_Bb3[128];

// ===================== helpers =====================
__device__ __forceinline__ uint32_t smem_u32(const void* p) {
    uint32_t a;
    asm("{ .reg .u64 t; cvta.to.shared.u64 t, %1; cvt.u32.u64 %0, t; }" : "=r"(a) : "l"(p));
    return a;
}
__device__ __forceinline__ uint32_t sw128(uint32_t off) { return off ^ ((off >> 3) & 0x70); }

__device__ __forceinline__ void ldsm_x4(uint32_t& r0, uint32_t& r1, uint32_t& r2, uint32_t& r3,
                                        uint32_t addr) {
    asm volatile("ldmatrix.sync.aligned.m8n8.x4.shared.b16 {%0,%1,%2,%3}, [%4];"
                 : "=r"(r0), "=r"(r1), "=r"(r2), "=r"(r3) : "r"(addr));
}
__device__ __forceinline__ void mma16816(float* d, const uint32_t* a, const uint32_t* b) {
    asm volatile(
        "mma.sync.aligned.m16n8k16.row.col.f32.bf16.bf16.f32 "
        "{%0,%1,%2,%3}, {%4,%5,%6,%7}, {%8,%9}, {%0,%1,%2,%3};"
        : "+f"(d[0]), "+f"(d[1]), "+f"(d[2]), "+f"(d[3])
        : "r"(a[0]), "r"(a[1]), "r"(a[2]), "r"(a[3]), "r"(b[0]), "r"(b[1]));
}

// ===================== expansion: [relu, B0..B4, 0, 0] =====================
// Knots t_j = (j-2)*2/3 - 1; quadratic uniform B-spline closed form.
__device__ __forceinline__ void expand8(float v, float e[8]) {
    e[0] = fmaxf(v, 0.0f);
    float u = (v + 2.3333333333333335f) * 1.5f;
#pragma unroll
    for (int j = 0; j < 5; j++) {
        float b;
        if (u < 0.0f || u >= 3.0f)      b = 0.0f;
        else if (u < 1.0f)              b = 0.5f * u * u;
        else if (u < 2.0f)              b = fmaf(-u, u, fmaf(3.0f, u, -1.5f));
        else { float t = 3.0f - u;      b = 0.5f * t * t; }
        e[1 + j] = b;
        u -= 1.0f;
    }
    e[6] = 0.0f; e[7] = 0.0f;
}

__device__ __forceinline__ void split_pack(const float* e, uint32_t* hw, uint32_t* lw) {
#pragma unroll
    for (int j = 0; j < 4; j++) {
        float a = e[2 * j], b = e[2 * j + 1];
        __nv_bfloat16 ah = __float2bfloat16(a), bh = __float2bfloat16(b);
        __nv_bfloat16 al = __float2bfloat16(a - __bfloat162float(ah));
        __nv_bfloat16 bl = __float2bfloat16(b - __bfloat162float(bh));
        hw[j] = (uint32_t)__bfloat16_as_ushort(ah) | ((uint32_t)__bfloat16_as_ushort(bh) << 16);
        lw[j] = (uint32_t)__bfloat16_as_ushort(al) | ((uint32_t)__bfloat16_as_ushort(bl) << 16);
    }
}

// ===================== weight prep: pre-swizzled bf16 hi/lo chunk images ======
// Image layout: chunk kc (64 K-slots = 8 features), row n (0..O-1), 128B/row,
// SW128 swizzle applied. k-slot j of feature f: j==0 base_w, 1..5 spline*scaler, else 0.
__global__ void prep_w(const float* __restrict__ bw, const float* __restrict__ sw,
                       const float* __restrict__ sc, unsigned char* __restrict__ Wh,
                       unsigned char* __restrict__ Wl, int F, int O) {
    int total = F * O;
    for (int idx = blockIdx.x * blockDim.x + threadIdx.x; idx < total;
         idx += gridDim.x * blockDim.x) {
        int n = idx / F, f = idx - n * F;
        int kc = f >> 3, funit = f & 7;
        float base = bw[n * F + f];
        float scl = sc[n * F + f];
        const float* sp = sw + (size_t)(n * F + f) * 5;
        float e[8];
        e[0] = base;
#pragma unroll
        for (int j = 0; j < 5; j++) e[1 + j] = sp[j] * scl;
        e[6] = 0.0f; e[7] = 0.0f;
        uint32_t hw[4], lw[4];
        split_pack(e, hw, lw);
        size_t off = (size_t)kc * (O * 128) + sw128((uint32_t)(n * 128 + funit * 16));
        *(uint4*)(Wh + off) = make_uint4(hw[0], hw[1], hw[2], hw[3]);
        *(uint4*)(Wl + off) = make_uint4(lw[0], lw[1], lw[2], lw[3]);
    }
}

// ===================== fused KAN conv: mma.sync bf16 3-split GEMM =============
// CTA tile: 128 positions x O outputs. K chunks of 64 (8 features x 8 slots).
// acc(fp32, regs) += Ah*Bh + Ah*Bl + Al*Bh.
template <int O, int C, int Hin, int Hout, int F, bool HASBN, int SPLITK, int WM, int WN>
__global__ void __launch_bounds__(256) kan_hmma(
    const float* __restrict__ in, const unsigned char* __restrict__ Wh,
    const unsigned char* __restrict__ Wl, const float* __restrict__ bnA,
    const float* __restrict__ bnB, float* __restrict__ out) {
    constexpr int HW = Hout * Hout;
    constexpr int CHUNKS = F / 8;
    constexpr int CPS = CHUNKS / SPLITK;
    constexpr int warpM = 128 / WM;       // 16 or 32
    constexpr int warpN = O / WN;         // 32 or 64
    constexpr int MT = warpM / 16;        // m16 tiles per warp
    constexpr int NT = warpN / 8;         // n8 tiles per warp

    extern __shared__ unsigned char smem[];
    unsigned char* Ah = smem;
    unsigned char* Al = smem + 16384;
    unsigned char* Bh = smem + 32768;
    unsigned char* Bl = Bh + O * 128;
    const uint32_t sbase = smem_u32(smem);
    const uint32_t AhU = sbase, AlU = sbase + 16384;
    const uint32_t BhU = sbase + 32768, BlU = BhU + O * 128;

    const int tid = threadIdx.x;
    const int wid = tid >> 5, lane = tid & 31;
    const int p0 = blockIdx.x * 128;
    const int kc0 = blockIdx.y * CPS;
    const int wm0 = (wid / WN) * warpM;
    const int wn0 = (wid % WN) * warpN;

    float acc[MT][NT][4];
#pragma unroll
    for (int i = 0; i < MT; i++)
#pragma unroll
        for (int j = 0; j < NT; j++)
#pragma unroll
            for (int k = 0; k < 4; k++) acc[i][j][k] = 0.0f;

    // per-thread invariant ldmatrix address components
    const uint32_t aRow = (uint32_t)(lane & 15);
    const uint32_t aColx = (uint32_t)((lane >> 4) << 4);
    const uint32_t bRow = (uint32_t)((lane & 7) + ((lane & 16) >> 1));
    const uint32_t bColx = (uint32_t)((lane & 8) << 1);

    for (int i = 0; i < CPS; i++) {
        const int kc = kc0 + i;
        if (i > 0) __syncthreads();  // protect SMEM reuse
        // ---- B tiles: flat copy of pre-swizzled chunk image ----
        {
            const uint4* sh = (const uint4*)(Wh + (size_t)kc * (O * 128));
            const uint4* sl = (const uint4*)(Wl + (size_t)kc * (O * 128));
            uint4* dh = (uint4*)Bh;
            uint4* dl = (uint4*)Bl;
#pragma unroll
            for (int u = tid; u < O * 8; u += 256) { dh[u] = sh[u]; dl[u] = sl[u]; }
        }
        // ---- A tiles: gather + BN + expand + bf16 split, swizzled STS.128 ----
#pragma unroll
        for (int t = 0; t < 4; t++) {
            int idx = tid + t * 256;            // 1024 = 128 pos x 8 feats
            int m = idx & 127, fl = idx >> 7;
            int p = p0 + m;
            int b = p / HW, s = p - b * HW;
            int oh = s / Hout, ow = s - oh * Hout;
            int f = kc * 8 + fl;
            int c = f >> 4, r = f & 15;
            int ih = oh * 2 + (r >> 2) - 1, iw = ow * 2 + (r & 3) - 1;
            float v = 0.0f;
            if ((unsigned)ih < (unsigned)Hin && (unsigned)iw < (unsigned)Hin) {
                v = in[((b * C + c) * Hin + ih) * Hin + iw];
                if (HASBN) v = fmaf(v, bnA[c], bnB[c]);
            }
            float e[8];
            expand8(v, e);
            uint32_t hw[4], lw[4];
            split_pack(e, hw, lw);
            uint32_t off = sw128((uint32_t)(m * 128 + fl * 16));
            *(uint4*)(Ah + off) = make_uint4(hw[0], hw[1], hw[2], hw[3]);
            *(uint4*)(Al + off) = make_uint4(lw[0], lw[1], lw[2], lw[3]);
        }
        __syncthreads();
        // ---- MMA: 4 K-steps of 16; per step 3 split terms ----
#pragma unroll
        for (int ks = 0; ks < 4; ks++) {
            const uint32_t kb = ks * 32;  // bytes
            uint32_t ah[MT][4], al[MT][4];
#pragma unroll
            for (int mt = 0; mt < MT; mt++) {
                uint32_t aoff = sw128((uint32_t)((wm0 + mt * 16 + aRow) * 128) + kb + aColx);
                ldsm_x4(ah[mt][0], ah[mt][1], ah[mt][2], ah[mt][3], AhU + aoff);
                ldsm_x4(al[mt][0], al[mt][1], al[mt][2], al[mt][3], AlU + aoff);
            }
#pragma unroll
            for (int np = 0; np < NT / 2; np++) {
                uint32_t boff =
                    sw128((uint32_t)((wn0 + np * 16 + bRow) * 128) + kb + bColx);
                uint32_t bh[4], bl[4];
                ldsm_x4(bh[0], bh[1], bh[2], bh[3], BhU + boff);
                ldsm_x4(bl[0], bl[1], bl[2], bl[3], BlU + boff);
#pragma unroll
                for (int mt = 0; mt < MT; mt++) {
#pragma unroll
                    for (int t = 0; t < 2; t++) {
                        mma16816(acc[mt][np * 2 + t], ah[mt], &bh[2 * t]);
                        mma16816(acc[mt][np * 2 + t], ah[mt], &bl[2 * t]);
                        mma16816(acc[mt][np * 2 + t], al[mt], &bh[2 * t]);
                    }
                }
            }
        }
    }

    // ---- epilogue: fragment c0,c1 -> row g; c2,c3 -> row g+8 ----
    const int g = lane >> 2, tg2 = (lane & 3) * 2;
#pragma unroll
    for (int mt = 0; mt < MT; mt++) {
#pragma unroll
        for (int nt = 0; nt < NT; nt++) {
#pragma unroll
            for (int half = 0; half < 2; half++) {
                int p = p0 + wm0 + mt * 16 + g + half * 8;
                int o0 = wn0 + nt * 8 + tg2;
                float v0 = acc[mt][nt][half * 2 + 0];
                float v1 = acc[mt][nt][half * 2 + 1];
                if (SPLITK == 1) {
                    int b = p / HW, s = p - b * HW;
                    out[((size_t)b * O + o0) * HW + s] = v0;
                    out[((size_t)b * O + o0 + 1) * HW + s] = v1;
                } else {
                    const size_t Ptot = (size_t)gridDim.x * 128;
                    out[((size_t)blockIdx.y * O + o0) * Ptot + p] = v0;
                    out[((size_t)blockIdx.y * O + o0 + 1) * Ptot + p] = v1;
                }
            }
        }
    }
}

// ===================== split-K reduce: partial[s][o][p] -> NCHW ===============
__global__ void splitk_reduce(const float* __restrict__ part, float* __restrict__ out,
                              int O, int P, int HW, int S) {
    int total = O * P;
    for (int idx = blockIdx.x * blockDim.x + threadIdx.x; idx < total;
         idx += gridDim.x * blockDim.x) {
        int o = idx / P, p = idx - o * P;
        float v = 0.0f;
        for (int s = 0; s < S; s++) v += part[((size_t)s * O + o) * P + p];
        int b = p / HW, sp = p - b * HW;
        out[((size_t)b * O + o) * HW + sp] = v;
    }
}

// ===================== batchnorm stats -> affine (a, b) =======================
__global__ void bn_stats(const float* __restrict__ y, int C, int HW,
                         const float* __restrict__ gamma, const float* __restrict__ beta,
                         float* __restrict__ A, float* __restrict__ Bv) {
    int c = blockIdx.x;
    int N = 512 * HW;
    float s = 0.0f, s2 = 0.0f;
    for (int i = threadIdx.x; i < N; i += blockDim.x) {
        int b = i / HW, sp = i - b * HW;
        float v = y[((size_t)b * C + c) * HW + sp];
        s += v; s2 = fmaf(v, v, s2);
    }
    __shared__ float sh[2][256];
    sh[0][threadIdx.x] = s; sh[1][threadIdx.x] = s2;
    __syncthreads();
    for (int st = 128; st > 0; st >>= 1) {
        if (threadIdx.x < st) {
            sh[0][threadIdx.x] += sh[0][threadIdx.x + st];
            sh[1][threadIdx.x] += sh[1][threadIdx.x + st];
        }
        __syncthreads();
    }
    if (threadIdx.x == 0) {
        float inv = 1.0f / (float)N;
        float m = sh[0][0] * inv;
        float var = fmaf(-m, m, sh[1][0] * inv);
        float a = gamma[c] * rsqrtf(var + 1e-5f);
        A[c] = a;
        Bv[c] = fmaf(-m, a, beta[c]);
    }
}

// ===================== head: BN3 + avgpool(2x2) + FC + sigmoid ================
__global__ void head_kernel(const float* __restrict__ y4, const float* __restrict__ A,
                            const float* __restrict__ Bv, const float* __restrict__ fcw,
                            const float* __restrict__ fcb, float* __restrict__ out) {
    int b = blockIdx.x;
    int c = threadIdx.x;  // 128
    const float* p = y4 + ((size_t)b * 128 + c) * 4;
    float m = 0.25f * (p[0] + p[1] + p[2] + p[3]);
    float t = fmaf(m, A[c], Bv[c]) * fcw[c];
    __shared__ float sh[128];
    sh[c] = t;
    __syncthreads();
    for (int st = 64; st > 0; st >>= 1) {
        if (c < st) sh[c] += sh[c + st];
        __syncthreads();
    }
    if (c == 0) {
        float z = sh[0] + fcb[0];
        out[b] = 1.0f / (1.0f + expf(-z));
    }
}

// ===================== launch =================================================
extern "C" void kernel_launch(void* const* d_in, const int* in_sizes, int n_in,
                              void* d_out, int out_size) {
    const float* x   = (const float*)d_in[0];
    const float* bw1 = (const float*)d_in[1];
    const float* sw1 = (const float*)d_in[2];
    const float* sc1 = (const float*)d_in[3];
    const float* bw2 = (const float*)d_in[4];
    const float* sw2 = (const float*)d_in[5];
    const float* sc2 = (const float*)d_in[6];
    const float* bw3 = (const float*)d_in[7];
    const float* sw3 = (const float*)d_in[8];
    const float* sc3 = (const float*)d_in[9];
    const float* bw4 = (const float*)d_in[10];
    const float* sw4 = (const float*)d_in[11];
    const float* sc4 = (const float*)d_in[12];
    const float* g1  = (const float*)d_in[13];
    const float* b1  = (const float*)d_in[14];
    const float* g2  = (const float*)d_in[15];
    const float* b2  = (const float*)d_in[16];
    const float* g3  = (const float*)d_in[17];
    const float* b3  = (const float*)d_in[18];
    const float* fcw = (const float*)d_in[19];
    const float* fcb = (const float*)d_in[20];

    unsigned char *Wh1, *Wl1, *Wh2, *Wl2, *Wh3, *Wl3, *Wh4, *Wl4;
    float *y1, *y2, *y3, *y4, *p3, *p4;
    float *A1, *Bv1, *A2, *Bv2, *A3, *Bv3;
    cudaGetSymbolAddress((void**)&Wh1, g_Wh1); cudaGetSymbolAddress((void**)&Wl1, g_Wl1);
    cudaGetSymbolAddress((void**)&Wh2, g_Wh2); cudaGetSymbolAddress((void**)&Wl2, g_Wl2);
    cudaGetSymbolAddress((void**)&Wh3, g_Wh3); cudaGetSymbolAddress((void**)&Wl3, g_Wl3);
    cudaGetSymbolAddress((void**)&Wh4, g_Wh4); cudaGetSymbolAddress((void**)&Wl4, g_Wl4);
    cudaGetSymbolAddress((void**)&y1, g_y1);   cudaGetSymbolAddress((void**)&y2, g_y2);
    cudaGetSymbolAddress((void**)&y3, g_y3);   cudaGetSymbolAddress((void**)&y4, g_y4);
    cudaGetSymbolAddress((void**)&p3, g_part3); cudaGetSymbolAddress((void**)&p4, g_part4);
    cudaGetSymbolAddress((void**)&A1, g_A1);   cudaGetSymbolAddress((void**)&Bv1, g_Bb1);
    cudaGetSymbolAddress((void**)&A2, g_A2);   cudaGetSymbolAddress((void**)&Bv2, g_Bb2);
    cudaGetSymbolAddress((void**)&A3, g_A3);   cudaGetSymbolAddress((void**)&Bv3, g_Bb3);

    const int smem1 = 32768 + 2 * 32 * 128;    // 40960
    const int smem2 = 32768 + 2 * 64 * 128;    // 49152
    const int smem3 = 32768 + 2 * 128 * 128;   // 65536
    cudaFuncSetAttribute((const void*)kan_hmma<32, 3, 32, 16, 48, false, 1, 8, 1>,
                         cudaFuncAttributeMaxDynamicSharedMemorySize, smem1);
    cudaFuncSetAttribute((const void*)kan_hmma<64, 32, 16, 8, 512, false, 1, 4, 2>,
                         cudaFuncAttributeMaxDynamicSharedMemorySize, smem2);
    cudaFuncSetAttribute((const void*)kan_hmma<128, 64, 8, 4, 1024, true, 2, 4, 2>,
                         cudaFuncAttributeMaxDynamicSharedMemorySize, smem3);
    cudaFuncSetAttribute((const void*)kan_hmma<128, 128, 4, 2, 2048, true, 8, 4, 2>,
                         cudaFuncAttributeMaxDynamicSharedMemorySize, smem3);

    // weight prep (bf16 hi/lo, pre-swizzled chunk images)
    prep_w<<<32, 256>>>(bw1, sw1, sc1, Wh1, Wl1, 48, 32);
    prep_w<<<128, 256>>>(bw2, sw2, sc2, Wh2, Wl2, 512, 64);
    prep_w<<<512, 256>>>(bw3, sw3, sc3, Wh3, Wl3, 1024, 128);
    prep_w<<<1024, 256>>>(bw4, sw4, sc4, Wh4, Wl4, 2048, 128);

    // L1: (512,3,32,32) -> (512,32,16,16)
    kan_hmma<32, 3, 32, 16, 48, false, 1, 8, 1><<<1024, 256, smem1>>>(
        x, Wh1, Wl1, nullptr, nullptr, y1);
    // L2: -> (512,64,8,8)
    kan_hmma<64, 32, 16, 8, 512, false, 1, 4, 2><<<256, 256, smem2>>>(
        y1, Wh2, Wl2, nullptr, nullptr, y2);
    bn_stats<<<64, 256>>>(y2, 64, 64, g1, b1, A1, Bv1);
    // L3 (BN1 fused into loader, split-K=2): -> (512,128,4,4)
    kan_hmma<128, 64, 8, 4, 1024, true, 2, 4, 2><<<dim3(64, 2), 256, smem3>>>(
        y2, Wh3, Wl3, A1, Bv1, p3);
    splitk_reduce<<<1024, 256>>>(p3, y3, 128, 8192, 16, 2);
    bn_stats<<<128, 256>>>(y3, 128, 16, g2, b2, A2, Bv2);
    // L4 (BN2 fused, split-K=8): -> (512,128,2,2)
    kan_hmma<128, 128, 4, 2, 2048, true, 8, 4, 2><<<dim3(16, 8), 256, smem3>>>(
        y3, Wh4, Wl4, A2, Bv2, p4);
    splitk_reduce<<<256, 256>>>(p4, y4, 128, 2048, 4, 8);
    bn_stats<<<128, 256>>>(y4, 128, 4, g3, b3, A3, Bv3);
    // head
    head_kernel<<<512, 128>>>(y4, A3, Bv3, fcw, fcb, (float*)d_out);
}